// round 1
// baseline (speedup 1.0000x reference)
#include <cuda_runtime.h>
#include <cstdint>

// ---------------------------------------------------------------------------
// Scratch (device globals; no allocation anywhere)
// ---------------------------------------------------------------------------
__device__ float g_x256[2 * 256 * 256];
__device__ float g_x128[2 * 128 * 128];
__device__ float g_x64 [2 * 64 * 64];
__device__ float g_h1 [(size_t)2 * 64 * 512 * 512];   // conv1 out / conv4 out (reused)
__device__ float g_h2 [(size_t)2 * 64 * 512 * 512];   // conv2 out
__device__ float g_f  [(size_t)2 * 81 * 512 * 512];   // conv3 logits
__device__ float g_cat[(size_t)2 * 5  * 512 * 512];   // concat of 5 scale outputs

// ---------------------------------------------------------------------------
// Nearest-neighbor downsample: out[n,j,i] = in[n, j*stride, i*stride]
// (matches arange(oh)*ih//oh for ih = oh*stride)
// ---------------------------------------------------------------------------
__global__ void downsample_kernel(const float* __restrict__ in, float* __restrict__ out,
                                  int OH, int OW, int stride)
{
    int idx = blockIdx.x * blockDim.x + threadIdx.x;
    int n = blockIdx.y;
    if (idx >= OH * OW) return;
    int oy = idx / OW, ox = idx - oy * OW;
    out[(size_t)n * OH * OW + idx] =
        in[(size_t)n * 512 * 512 + (size_t)(oy * stride) * 512 + ox * stride];
}

// ---------------------------------------------------------------------------
// Direct 3x3 SAME conv (cross-correlation, OIHW weights), optional ReLU.
// 16x16 output tile / block (256 threads), each thread owns 1 pixel and
// COUT accumulators. Per input channel: 18x18 patch + COUT*9 weights staged
// in smem (weights padded to 12 floats/co for LDS.128), with global->reg
// prefetch of the next channel overlapping the compute phase.
// ---------------------------------------------------------------------------
template<int COUT, bool RELU, int MINB>
__global__ __launch_bounds__(256, MINB)
void conv3x3_kernel(const float* __restrict__ in, const float* __restrict__ wt,
                    const float* __restrict__ bias, float* __restrict__ out,
                    int C, int H, int W)
{
    __shared__ float patch[18 * 18];
    __shared__ float ws[COUT * 12];

    const int t  = threadIdx.x;
    const int tx = t & 15;
    const int ty = t >> 4;
    const int x0 = blockIdx.x << 4;
    const int y0 = blockIdx.y << 4;
    const int n  = blockIdx.z;
    const size_t HW = (size_t)H * W;

    float acc[COUT];
#pragma unroll
    for (int co = 0; co < COUT; co++) acc[co] = 0.f;

    const float* inn = in + (size_t)n * C * HW;

    float pv[2];
    float pw[3];

    auto prefetch = [&](int c) {
#pragma unroll
        for (int j = 0; j < 2; j++) {
            int idx = t + j * 256;
            float v = 0.f;
            if (idx < 18 * 18) {
                int py = idx / 18, px = idx - py * 18;
                int gy = y0 + py - 1, gx = x0 + px - 1;
                if (gy >= 0 && gy < H && gx >= 0 && gx < W)
                    v = inn[(size_t)c * HW + (size_t)gy * W + gx];
            }
            pv[j] = v;
        }
#pragma unroll
        for (int j = 0; j < 3; j++) {
            pw[j] = 0.f;
            int idx = t + j * 256;
            if (idx < COUT * 9) {
                int co = idx / 9, k = idx - co * 9;
                pw[j] = wt[((size_t)co * C + c) * 9 + k];
            }
        }
    };

    auto store_sm = [&]() {
#pragma unroll
        for (int j = 0; j < 2; j++) {
            int idx = t + j * 256;
            if (idx < 18 * 18) patch[idx] = pv[j];
        }
#pragma unroll
        for (int j = 0; j < 3; j++) {
            int idx = t + j * 256;
            if (idx < COUT * 9) {
                int co = idx / 9, k = idx - co * 9;
                ws[co * 12 + k] = pw[j];
            }
        }
    };

    prefetch(0);
    for (int c = 0; c < C; c++) {
        __syncthreads();            // previous compute done reading smem
        store_sm();
        __syncthreads();            // smem ready
        if (c + 1 < C) prefetch(c + 1);   // overlap next loads with compute

        float v[9];
#pragma unroll
        for (int ky = 0; ky < 3; ky++)
#pragma unroll
            for (int kx = 0; kx < 3; kx++)
                v[ky * 3 + kx] = patch[(ty + ky) * 18 + tx + kx];

#pragma unroll
        for (int co = 0; co < COUT; co++) {
            const float4* w4 = reinterpret_cast<const float4*>(&ws[co * 12]);
            float4 a = w4[0];
            float4 b = w4[1];
            float  c8 = ws[co * 12 + 8];
            acc[co] += v[0] * a.x + v[1] * a.y + v[2] * a.z + v[3] * a.w
                     + v[4] * b.x + v[5] * b.y + v[6] * b.z + v[7] * b.w
                     + v[8] * c8;
        }
    }

    const int oy = y0 + ty, ox = x0 + tx;
    float* outn = out + (size_t)n * COUT * HW;
#pragma unroll
    for (int co = 0; co < COUT; co++) {
        float r = acc[co] + __ldg(&bias[co]);
        if (RELU) r = fmaxf(r, 0.f);
        outn[(size_t)co * HW + (size_t)oy * W + ox] = r;
    }
}

// ---------------------------------------------------------------------------
// Per-pixel: softmax over the 81 filter logits, apply the 9x9 dynamic conv
// to the (zero-padded) scale input, and write the result nearest-upsampled
// into channel `ch` of the 5-channel concat buffer (512x512).
// ---------------------------------------------------------------------------
__global__ __launch_bounds__(128)
void softmax_apply_kernel(const float* __restrict__ f, const float* __restrict__ s,
                          float* __restrict__ cat, int H, int W, int ch, int factor)
{
    int idx = blockIdx.x * blockDim.x + threadIdx.x;
    int n = blockIdx.y;
    if (idx >= H * W) return;
    int iy = idx / W, ix = idx - iy * W;

    const float* fn = f + (size_t)n * 81 * H * W + idx;
    float lg[81];
    float mx = -1e30f;
#pragma unroll
    for (int k = 0; k < 81; k++) {
        lg[k] = fn[(size_t)k * H * W];
        mx = fmaxf(mx, lg[k]);
    }
    float sum = 0.f;
#pragma unroll
    for (int k = 0; k < 81; k++) {
        lg[k] = __expf(lg[k] - mx);
        sum += lg[k];
    }
    float inv = 1.f / sum;

    const float* sn = s + (size_t)n * H * W;
    float outv = 0.f;
#pragma unroll
    for (int dy = 0; dy < 9; dy++) {
        int yy = iy + dy - 4;
#pragma unroll
        for (int dx = 0; dx < 9; dx++) {
            int xx = ix + dx - 4;
            float xv = (yy >= 0 && yy < H && xx >= 0 && xx < W)
                         ? sn[(size_t)yy * W + xx] : 0.f;
            outv += lg[dy * 9 + dx] * xv;
        }
    }
    outv *= inv;

    float* cn = cat + ((size_t)n * 5 + ch) * 512 * 512;
    int oy0 = iy * factor, ox0 = ix * factor;
    for (int ry = 0; ry < factor; ry++)
        for (int rx = 0; rx < factor; rx++)
            cn[(size_t)(oy0 + ry) * 512 + ox0 + rx] = outv;
}

// ---------------------------------------------------------------------------
// Launch
// ---------------------------------------------------------------------------
extern "C" void kernel_launch(void* const* d_in, const int* in_sizes, int n_in,
                              void* d_out, int out_size)
{
    const float* x   = (const float*)d_in[0];
    const float* g   = (const float*)d_in[1];
    const float* fWa = (const float*)d_in[2];   // (5,64,1,3,3)
    const float* fba = (const float*)d_in[3];   // (5,64)
    const float* fWb = (const float*)d_in[4];   // (5,64,64,3,3)
    const float* fbb = (const float*)d_in[5];   // (5,64)
    const float* fWc = (const float*)d_in[6];   // (5,81,64,3,3)
    const float* fbc = (const float*)d_in[7];   // (5,81)
    const float* W2a = (const float*)d_in[8];   // (64,5,3,3)
    const float* b2a = (const float*)d_in[9];   // (64)
    const float* W2b = (const float*)d_in[10];  // (1,64,3,3)
    const float* b2b = (const float*)d_in[11];  // (1)
    float* out = (float*)d_out;

    float *x256, *x128, *x64p, *h1, *h2, *fbuf, *cat;
    cudaGetSymbolAddress((void**)&x256, g_x256);
    cudaGetSymbolAddress((void**)&x128, g_x128);
    cudaGetSymbolAddress((void**)&x64p, g_x64);
    cudaGetSymbolAddress((void**)&h1,   g_h1);
    cudaGetSymbolAddress((void**)&h2,   g_h2);
    cudaGetSymbolAddress((void**)&fbuf, g_f);
    cudaGetSymbolAddress((void**)&cat,  g_cat);

    // Downsample x -> 256/128/64 (nearest = strided sampling)
    downsample_kernel<<<dim3((256 * 256 + 255) / 256, 2), 256>>>(x, x256, 256, 256, 2);
    downsample_kernel<<<dim3((128 * 128 + 255) / 256, 2), 256>>>(x, x128, 128, 128, 4);
    downsample_kernel<<<dim3((64 * 64 + 255) / 256, 2), 256>>>(x, x64p, 64, 64, 8);

    const float* sin[5] = { x, x256, x128, x64p, g };
    const int    hs[5]  = { 512, 256, 128, 64, 512 };

    for (int i = 0; i < 5; i++) {
        int H = hs[i], W = H;
        dim3 grid(W / 16, H / 16, 2);
        conv3x3_kernel<64, true, 2><<<grid, 256>>>(
            sin[i], fWa + (size_t)i * 64 * 9, fba + i * 64, h1, 1, H, W);
        conv3x3_kernel<64, true, 2><<<grid, 256>>>(
            h1, fWb + (size_t)i * 64 * 64 * 9, fbb + i * 64, h2, 64, H, W);
        conv3x3_kernel<81, false, 1><<<grid, 256>>>(
            h2, fWc + (size_t)i * 81 * 64 * 9, fbc + i * 81, fbuf, 64, H, W);
        int np = H * W;
        softmax_apply_kernel<<<dim3((np + 127) / 128, 2), 128>>>(
            fbuf, sin[i], cat, H, W, i, 512 / H);
    }

    dim3 gridF(512 / 16, 512 / 16, 2);
    conv3x3_kernel<64, true, 2><<<gridF, 256>>>(cat, W2a, b2a, h1, 5, 512, 512);
    conv3x3_kernel<1, false, 2><<<gridF, 256>>>(h1, W2b, b2b, out, 64, 512, 512);
}

// round 2
// speedup vs baseline: 1.4094x; 1.4094x over previous
#include <cuda_runtime.h>
#include <cstdint>

typedef unsigned long long ull;

// ---------------------------------------------------------------------------
// Scratch (device globals; no allocation anywhere)
// ---------------------------------------------------------------------------
__device__ float g_x256[2 * 256 * 256];
__device__ float g_x128[2 * 128 * 128];
__device__ float g_x64 [2 * 64 * 64];
__device__ float g_h1 [(size_t)2 * 64 * 512 * 512];
__device__ float g_h2 [(size_t)2 * 64 * 512 * 512];
__device__ float g_f  [(size_t)2 * 81 * 512 * 512];
__device__ float g_cat[(size_t)2 * 5  * 512 * 512];

// ---------------------------------------------------------------------------
// Packed f32x2 helpers (sm_103a FFMA2 path)
// ---------------------------------------------------------------------------
__device__ __forceinline__ void ffma2(ull& acc, ull a, ull b) {
    asm("fma.rn.f32x2 %0, %1, %2, %0;" : "+l"(acc) : "l"(a), "l"(b));
}
__device__ __forceinline__ ull packdup(float v) {
    ull r;
    asm("mov.b64 %0, {%1, %1};" : "=l"(r) : "f"(v));
    return r;
}
__device__ __forceinline__ void unpack2(ull v, float& lo, float& hi) {
    asm("mov.b64 {%0, %1}, %2;" : "=f"(lo), "=f"(hi) : "l"(v));
}

// ---------------------------------------------------------------------------
// Nearest-neighbor downsample
// ---------------------------------------------------------------------------
__global__ void downsample_kernel(const float* __restrict__ in, float* __restrict__ out,
                                  int OH, int OW, int stride)
{
    int idx = blockIdx.x * blockDim.x + threadIdx.x;
    int n = blockIdx.y;
    if (idx >= OH * OW) return;
    int oy = idx / OW, ox = idx - oy * OW;
    out[(size_t)n * OH * OW + idx] =
        in[(size_t)n * 512 * 512 + (size_t)(oy * stride) * 512 + ox * stride];
}

// ---------------------------------------------------------------------------
// Direct 3x3 SAME conv with packed-f32x2 math.
// Block: 256 threads; output tile 32 wide x 16 high. Thread (px,ty) owns the
// two pixels (2*px, 2*px+1) in row ty. Output channels processed in groups of
// GP channel-PAIRS; f32x2 lanes = (co_even, co_odd). Each weight pair (5 LDS)
// feeds 18 FFMA2 (2 pixels x 9 taps). Smem double-buffered, 1 barrier/channel,
// global->register prefetch of the next channel's patch + weights.
// ---------------------------------------------------------------------------
template<int COUT, bool RELU>
__global__ __launch_bounds__(256)
void conv3x3_kernel(const float* __restrict__ in, const float* __restrict__ wt,
                    const float* __restrict__ bias, float* __restrict__ out,
                    int C, int H, int W)
{
    constexpr int GP = (COUT == 81) ? 14 : (COUT >= 64 ? 16 : 1);
    constexpr int NPAIR = (COUT + 1) / 2;
    constexpr int NG = (NPAIR + GP - 1) / GP;
    constexpr int PS = 35;                  // patch row stride (odd: no bank clash)
    constexpr int WELEM = GP * 18;          // floats of weights per group per channel
    constexpr int WITER = (WELEM + 255) / 256;

    __shared__ float patch[2][18 * PS];
    __shared__ __align__(16) float ws[2][GP * 20];

    const int t   = threadIdx.x;
    const int px  = t & 15;                 // pixel-pair index (x = 2*px, 2*px+1)
    const int ty  = t >> 4;
    const int x0  = blockIdx.x << 5;
    const int y0  = blockIdx.y << 4;
    const int n   = blockIdx.z;
    const size_t HW = (size_t)H * W;

    const float* inn = in + (size_t)n * C * HW;

    float pv[3];
    float pw[WITER];

    // prefetch channel c of group g into registers
    auto prefetch = [&](int g, int c) {
#pragma unroll
        for (int j = 0; j < 3; j++) {
            int e = t + j * 256;
            float v = 0.f;
            if (e < 18 * PS) {
                int r = e / PS, cc = e - r * PS;
                int gy = y0 + r - 1, gx = x0 + cc - 1;
                if (cc < 34 && gy >= 0 && gy < H && gx >= 0 && gx < W)
                    v = inn[(size_t)c * HW + (size_t)gy * W + gx];
            }
            pv[j] = v;
        }
#pragma unroll
        for (int j = 0; j < WITER; j++) {
            pw[j] = 0.f;
            int e = t + j * 256;
            if (e < WELEM) {
                // ordering (p, lane, k): contiguous 9-float runs in global
                int p = e / 18, r = e - p * 18;
                int lane = r / 9, k = r - lane * 9;
                int co = 2 * (g * GP + p) + lane;
                if (co < COUT)
                    pw[j] = wt[((size_t)co * C + c) * 9 + k];
            }
        }
    };

    auto store_sm = [&](int b) {
#pragma unroll
        for (int j = 0; j < 3; j++) {
            int e = t + j * 256;
            if (e < 18 * PS) patch[b][e] = pv[j];
        }
#pragma unroll
        for (int j = 0; j < WITER; j++) {
            int e = t + j * 256;
            if (e < WELEM) {
                int p = e / 18, r = e - p * 18;
                int lane = r / 9, k = r - lane * 9;
                ws[b][p * 20 + 2 * k + lane] = pw[j];
            }
        }
    };

#pragma unroll 1
    for (int g = 0; g < NG; ++g) {
        ull accA[GP], accB[GP];
#pragma unroll
        for (int p = 0; p < GP; p++) { accA[p] = 0ull; accB[p] = 0ull; }

        prefetch(g, 0);
#pragma unroll 1
        for (int c = 0; c < C; ++c) {
            int b = c & 1;
            store_sm(b);
            __syncthreads();
            if (c + 1 < C) prefetch(g, c + 1);

            // 12 patch values (4 cols x 3 rows) shared by the 2 pixels
            const float* pb = patch[b];
            ull dup[12];
#pragma unroll
            for (int ky = 0; ky < 3; ky++)
#pragma unroll
                for (int j = 0; j < 4; j++)
                    dup[ky * 4 + j] = packdup(pb[(ty + ky) * PS + 2 * px + j]);

            const float* wb = ws[b];
#pragma unroll
            for (int p = 0; p < GP; p++) {
                ull w[9];
                const ulonglong2* q = reinterpret_cast<const ulonglong2*>(wb + p * 20);
                ulonglong2 q0 = q[0], q1 = q[1], q2 = q[2], q3 = q[3];
                w[0] = q0.x; w[1] = q0.y; w[2] = q1.x; w[3] = q1.y;
                w[4] = q2.x; w[5] = q2.y; w[6] = q3.x; w[7] = q3.y;
                w[8] = *reinterpret_cast<const ull*>(wb + p * 20 + 16);
#pragma unroll
                for (int ky = 0; ky < 3; ky++)
#pragma unroll
                    for (int kx = 0; kx < 3; kx++) {
                        ffma2(accA[p], dup[ky * 4 + kx],     w[ky * 3 + kx]);
                        ffma2(accB[p], dup[ky * 4 + kx + 1], w[ky * 3 + kx]);
                    }
            }
        }

        // epilogue for this channel group
        {
            const int oy = y0 + ty;
            const int ox = x0 + 2 * px;
            float* outp = out + (size_t)n * COUT * HW + (size_t)oy * W + ox;
#pragma unroll
            for (int p = 0; p < GP; p++) {
                int co0 = 2 * (g * GP + p);
                if (co0 < COUT) {
                    float a0, a1, b0, b1;
                    unpack2(accA[p], a0, a1);
                    unpack2(accB[p], b0, b1);
                    float bi0 = __ldg(&bias[co0]);
                    float r0 = a0 + bi0, r1 = b0 + bi0;
                    if (RELU) { r0 = fmaxf(r0, 0.f); r1 = fmaxf(r1, 0.f); }
                    *reinterpret_cast<float2*>(outp + (size_t)co0 * HW) = make_float2(r0, r1);
                    if (co0 + 1 < COUT) {
                        float bi1 = __ldg(&bias[co0 + 1]);
                        float s0 = a1 + bi1, s1 = b1 + bi1;
                        if (RELU) { s0 = fmaxf(s0, 0.f); s1 = fmaxf(s1, 0.f); }
                        *reinterpret_cast<float2*>(outp + (size_t)(co0 + 1) * HW) = make_float2(s0, s1);
                    }
                }
            }
        }
        __syncthreads();   // buffers safe to overwrite by next group
    }
}

// ---------------------------------------------------------------------------
// Softmax(81) + 9x9 dynamic conv + nearest upsample into concat channel
// ---------------------------------------------------------------------------
__global__ __launch_bounds__(128)
void softmax_apply_kernel(const float* __restrict__ f, const float* __restrict__ s,
                          float* __restrict__ cat, int H, int W, int ch, int factor)
{
    int idx = blockIdx.x * blockDim.x + threadIdx.x;
    int n = blockIdx.y;
    if (idx >= H * W) return;
    int iy = idx / W, ix = idx - iy * W;

    const float* fn = f + (size_t)n * 81 * H * W + idx;
    float lg[81];
    float mx = -1e30f;
#pragma unroll
    for (int k = 0; k < 81; k++) {
        lg[k] = fn[(size_t)k * H * W];
        mx = fmaxf(mx, lg[k]);
    }
    float sum = 0.f;
#pragma unroll
    for (int k = 0; k < 81; k++) {
        lg[k] = __expf(lg[k] - mx);
        sum += lg[k];
    }
    float inv = 1.f / sum;

    const float* sn = s + (size_t)n * H * W;
    float outv = 0.f;
#pragma unroll
    for (int dy = 0; dy < 9; dy++) {
        int yy = iy + dy - 4;
#pragma unroll
        for (int dx = 0; dx < 9; dx++) {
            int xx = ix + dx - 4;
            float xv = (yy >= 0 && yy < H && xx >= 0 && xx < W)
                         ? sn[(size_t)yy * W + xx] : 0.f;
            outv += lg[dy * 9 + dx] * xv;
        }
    }
    outv *= inv;

    float* cn = cat + ((size_t)n * 5 + ch) * 512 * 512;
    int oy0 = iy * factor, ox0 = ix * factor;
    for (int ry = 0; ry < factor; ry++)
        for (int rx = 0; rx < factor; rx++)
            cn[(size_t)(oy0 + ry) * 512 + ox0 + rx] = outv;
}

// ---------------------------------------------------------------------------
// Launch
// ---------------------------------------------------------------------------
extern "C" void kernel_launch(void* const* d_in, const int* in_sizes, int n_in,
                              void* d_out, int out_size)
{
    const float* x   = (const float*)d_in[0];
    const float* g   = (const float*)d_in[1];
    const float* fWa = (const float*)d_in[2];
    const float* fba = (const float*)d_in[3];
    const float* fWb = (const float*)d_in[4];
    const float* fbb = (const float*)d_in[5];
    const float* fWc = (const float*)d_in[6];
    const float* fbc = (const float*)d_in[7];
    const float* W2a = (const float*)d_in[8];
    const float* b2a = (const float*)d_in[9];
    const float* W2b = (const float*)d_in[10];
    const float* b2b = (const float*)d_in[11];
    float* out = (float*)d_out;

    float *x256, *x128, *x64p, *h1, *h2, *fbuf, *cat;
    cudaGetSymbolAddress((void**)&x256, g_x256);
    cudaGetSymbolAddress((void**)&x128, g_x128);
    cudaGetSymbolAddress((void**)&x64p, g_x64);
    cudaGetSymbolAddress((void**)&h1,   g_h1);
    cudaGetSymbolAddress((void**)&h2,   g_h2);
    cudaGetSymbolAddress((void**)&fbuf, g_f);
    cudaGetSymbolAddress((void**)&cat,  g_cat);

    downsample_kernel<<<dim3((256 * 256 + 255) / 256, 2), 256>>>(x, x256, 256, 256, 2);
    downsample_kernel<<<dim3((128 * 128 + 255) / 256, 2), 256>>>(x, x128, 128, 128, 4);
    downsample_kernel<<<dim3((64 * 64 + 255) / 256, 2), 256>>>(x, x64p, 64, 64, 8);

    const float* sin[5] = { x, x256, x128, x64p, g };
    const int    hs[5]  = { 512, 256, 128, 64, 512 };

    for (int i = 0; i < 5; i++) {
        int H = hs[i], W = H;
        dim3 grid(W / 32, H / 16, 2);
        conv3x3_kernel<64, true><<<grid, 256>>>(
            sin[i], fWa + (size_t)i * 64 * 9, fba + i * 64, h1, 1, H, W);
        conv3x3_kernel<64, true><<<grid, 256>>>(
            h1, fWb + (size_t)i * 64 * 64 * 9, fbb + i * 64, h2, 64, H, W);
        conv3x3_kernel<81, false><<<grid, 256>>>(
            h2, fWc + (size_t)i * 81 * 64 * 9, fbc + i * 81, fbuf, 64, H, W);
        int np = H * W;
        softmax_apply_kernel<<<dim3((np + 127) / 128, 2), 128>>>(
            fbuf, sin[i], cat, H, W, i, 512 / H);
    }

    dim3 gridF(512 / 32, 512 / 16, 2);
    conv3x3_kernel<64, true><<<gridF, 256>>>(cat, W2a, b2a, h1, 5, 512, 512);
    conv3x3_kernel<1, false><<<gridF, 256>>>(h1, W2b, b2b, out, 64, 512, 512);
}

// round 3
// speedup vs baseline: 1.5590x; 1.1061x over previous
#include <cuda_runtime.h>
#include <cstdint>

typedef unsigned long long ull;

// ---------------------------------------------------------------------------
// Scratch (device globals; no allocation anywhere)
// ---------------------------------------------------------------------------
__device__ float g_x256[2 * 256 * 256];
__device__ float g_x128[2 * 128 * 128];
__device__ float g_x64 [2 * 64 * 64];
__device__ float g_h1 [(size_t)2 * 64 * 512 * 512];
__device__ float g_h2 [(size_t)2 * 64 * 512 * 512];
__device__ float g_f  [(size_t)2 * 81 * 512 * 512];
__device__ float g_cat[(size_t)2 * 5  * 512 * 512];

// ---------------------------------------------------------------------------
// Packed f32x2 helpers (sm_103a FFMA2 path)
// ---------------------------------------------------------------------------
__device__ __forceinline__ void ffma2(ull& acc, ull a, ull b) {
    asm("fma.rn.f32x2 %0, %1, %2, %0;" : "+l"(acc) : "l"(a), "l"(b));
}
__device__ __forceinline__ ull packdup(float v) {
    ull r;
    asm("mov.b64 %0, {%1, %1};" : "=l"(r) : "f"(v));
    return r;
}
__device__ __forceinline__ void unpack2(ull v, float& lo, float& hi) {
    asm("mov.b64 {%0, %1}, %2;" : "=f"(lo), "=f"(hi) : "l"(v));
}

// ---------------------------------------------------------------------------
// Nearest-neighbor downsample
// ---------------------------------------------------------------------------
__global__ void downsample_kernel(const float* __restrict__ in, float* __restrict__ out,
                                  int OH, int OW, int stride)
{
    int idx = blockIdx.x * blockDim.x + threadIdx.x;
    int n = blockIdx.y;
    if (idx >= OH * OW) return;
    int oy = idx / OW, ox = idx - oy * OW;
    out[(size_t)n * OH * OW + idx] =
        in[(size_t)n * 512 * 512 + (size_t)(oy * stride) * 512 + ox * stride];
}

// ---------------------------------------------------------------------------
// Generic direct 3x3 SAME conv, packed-f32x2 math.
// 128 threads, output tile 32x8. Thread (px,ty) owns pixels (2px, 2px+1) of
// row ty. COUT processed in groups of GP channel-pairs (f32x2 lanes = co
// even/odd). TWO input channels per barrier stage, double-buffered smem,
// global->reg prefetch overlapping compute.
// ---------------------------------------------------------------------------
template<int COUT, bool RELU>
__global__ __launch_bounds__(128, 3)
void conv3x3_kernel(const float* __restrict__ in, const float* __restrict__ wt,
                    const float* __restrict__ bias, float* __restrict__ out,
                    int C, int H, int W)
{
    constexpr int GP = (COUT == 81) ? 14 : (COUT >= 64 ? 16 : (COUT + 1) / 2);
    constexpr int NPAIR = (COUT + 1) / 2;
    constexpr int NG = (NPAIR + GP - 1) / GP;
    constexpr int PS = 35;            // patch row stride
    constexpr int ROWS = 10;          // 8 + halo 2
    constexpr int PELEM = ROWS * PS;  // 350
    constexpr int WELEM = GP * 18;    // weight floats per channel per group
    constexpr int WITER = (WELEM + 127) / 128;

    __shared__ float patch[2][2][PELEM];
    __shared__ __align__(16) float ws[2][2][GP * 20];

    const int t  = threadIdx.x;
    const int px = t & 15;
    const int ty = t >> 4;            // 0..7
    const int x0 = blockIdx.x << 5;
    const int y0 = blockIdx.y << 3;
    const int n  = blockIdx.z;
    const size_t HW = (size_t)H * W;
    const int NS = (C + 1) / 2;       // stages

    const float* inn = in + (size_t)n * C * HW;

    float pv[2][3];
    float pw[2][WITER];

    auto prefetch = [&](int g, int s) {
#pragma unroll
        for (int ch = 0; ch < 2; ch++) {
            int c = 2 * s + ch;
            if (c < C) {
#pragma unroll
                for (int j = 0; j < 3; j++) {
                    int e = t + j * 128;
                    float v = 0.f;
                    if (e < PELEM) {
                        int r = e / PS, cc = e - r * PS;
                        int gy = y0 + r - 1, gx = x0 + cc - 1;
                        if (cc < 34 && gy >= 0 && gy < H && gx >= 0 && gx < W)
                            v = inn[(size_t)c * HW + (size_t)gy * W + gx];
                    }
                    pv[ch][j] = v;
                }
#pragma unroll
                for (int j = 0; j < WITER; j++) {
                    pw[ch][j] = 0.f;
                    int e = t + j * 128;
                    if (e < WELEM) {
                        int p = e / 18, r = e - p * 18;
                        int lane = r / 9, k = r - lane * 9;
                        int co = 2 * (g * GP + p) + lane;
                        if (co < COUT)
                            pw[ch][j] = wt[((size_t)co * C + c) * 9 + k];
                    }
                }
            }
        }
    };

    auto store_sm = [&](int b, int s) {
#pragma unroll
        for (int ch = 0; ch < 2; ch++) {
            if (2 * s + ch < C) {
#pragma unroll
                for (int j = 0; j < 3; j++) {
                    int e = t + j * 128;
                    if (e < PELEM) patch[b][ch][e] = pv[ch][j];
                }
#pragma unroll
                for (int j = 0; j < WITER; j++) {
                    int e = t + j * 128;
                    if (e < WELEM) {
                        int p = e / 18, r = e - p * 18;
                        int lane = r / 9, k = r - lane * 9;
                        ws[b][ch][p * 20 + 2 * k + lane] = pw[ch][j];
                    }
                }
            }
        }
    };

#pragma unroll 1
    for (int g = 0; g < NG; ++g) {
        ull accA[GP], accB[GP];
#pragma unroll
        for (int p = 0; p < GP; p++) { accA[p] = 0ull; accB[p] = 0ull; }

        prefetch(g, 0);
#pragma unroll 1
        for (int s = 0; s < NS; ++s) {
            int b = s & 1;
            store_sm(b, s);
            __syncthreads();
            if (s + 1 < NS) prefetch(g, s + 1);

#pragma unroll
            for (int ch = 0; ch < 2; ch++) {
                if (2 * s + ch < C) {
                    const float* pb = patch[b][ch];
                    ull dup[12];
#pragma unroll
                    for (int ky = 0; ky < 3; ky++)
#pragma unroll
                        for (int j = 0; j < 4; j++)
                            dup[ky * 4 + j] = packdup(pb[(ty + ky) * PS + 2 * px + j]);

                    const float* wb = ws[b][ch];
#pragma unroll
                    for (int p = 0; p < GP; p++) {
                        ull w[9];
                        const ulonglong2* q = reinterpret_cast<const ulonglong2*>(wb + p * 20);
                        ulonglong2 q0 = q[0], q1 = q[1], q2 = q[2], q3 = q[3];
                        w[0] = q0.x; w[1] = q0.y; w[2] = q1.x; w[3] = q1.y;
                        w[4] = q2.x; w[5] = q2.y; w[6] = q3.x; w[7] = q3.y;
                        w[8] = *reinterpret_cast<const ull*>(wb + p * 20 + 16);
#pragma unroll
                        for (int ky = 0; ky < 3; ky++)
#pragma unroll
                            for (int kx = 0; kx < 3; kx++) {
                                ffma2(accA[p], dup[ky * 4 + kx],     w[ky * 3 + kx]);
                                ffma2(accB[p], dup[ky * 4 + kx + 1], w[ky * 3 + kx]);
                            }
                    }
                }
            }
        }

        {
            const int oy = y0 + ty;
            const int ox = x0 + 2 * px;
            float* outp = out + (size_t)n * COUT * HW + (size_t)oy * W + ox;
#pragma unroll
            for (int p = 0; p < GP; p++) {
                int co0 = 2 * (g * GP + p);
                if (co0 < COUT) {
                    float a0, a1, b0, b1;
                    unpack2(accA[p], a0, a1);
                    unpack2(accB[p], b0, b1);
                    float bi0 = __ldg(&bias[co0]);
                    float r0 = a0 + bi0, r1 = b0 + bi0;
                    if (RELU) { r0 = fmaxf(r0, 0.f); r1 = fmaxf(r1, 0.f); }
                    *reinterpret_cast<float2*>(outp + (size_t)co0 * HW) = make_float2(r0, r1);
                    if (co0 + 1 < COUT) {
                        float bi1 = __ldg(&bias[co0 + 1]);
                        float s0 = a1 + bi1, s1 = b1 + bi1;
                        if (RELU) { s0 = fmaxf(s0, 0.f); s1 = fmaxf(s1, 0.f); }
                        *reinterpret_cast<float2*>(outp + (size_t)(co0 + 1) * HW) = make_float2(s0, s1);
                    }
                }
            }
        }
        __syncthreads();
    }
}

// ---------------------------------------------------------------------------
// Fused conv1(1->64,relu) + conv2(64->64,relu). Input patch loaded to smem
// ONCE; conv1 output tiles (with conv2 halo) recomputed in smem per 2-channel
// stage; conv2 weights streamed global->reg->smem. No activation LDG in the
// mainloop, no h1 traffic at all.
// ---------------------------------------------------------------------------
__global__ __launch_bounds__(128, 3)
void conv12_kernel(const float* __restrict__ x, const float* __restrict__ w1,
                   const float* __restrict__ b1, const float* __restrict__ w2,
                   const float* __restrict__ b2, float* __restrict__ out,
                   int H, int W)
{
    constexpr int GP = 16, NG = 2, COUT = 64;
    constexpr int PS = 35, ROWS = 10;
    constexpr int XPS = 37, XROWS = 12;         // input halo tile
    constexpr int WELEM = GP * 18;

    __shared__ float xpatch[XROWS * XPS];       // origin (y0-2, x0-2)
    __shared__ float w1s[64 * 10];              // 9 taps + bias per channel
    __shared__ float cbuf[2][2][ROWS * PS];     // conv1-out tiles (relu'd)
    __shared__ __align__(16) float ws[2][2][GP * 20];

    const int t  = threadIdx.x;
    const int px = t & 15;
    const int ty = t >> 4;
    const int x0 = blockIdx.x << 5;
    const int y0 = blockIdx.y << 3;
    const int n  = blockIdx.z;
    const size_t HW = (size_t)H * W;

    // one-time loads
    const float* xn = x + (size_t)n * HW;
#pragma unroll
    for (int j = 0; j < 4; j++) {
        int e = t + j * 128;
        if (e < XROWS * XPS) {
            int r = e / XPS, cc = e - r * XPS;
            int gy = y0 + r - 2, gx = x0 + cc - 2;
            float v = 0.f;
            if (cc < 36 && gy >= 0 && gy < H && gx >= 0 && gx < W)
                v = xn[(size_t)gy * W + gx];
            xpatch[e] = v;
        }
    }
#pragma unroll
    for (int j = 0; j < 5; j++) {
        int e = t + j * 128;
        if (e < 640) {
            int c = e / 10, k = e - c * 10;
            w1s[e] = (k < 9) ? w1[c * 9 + k] : b1[c];
        }
    }
    __syncthreads();

    float pw[2][3];
    auto prefetch_w = [&](int g, int s) {
#pragma unroll
        for (int ch = 0; ch < 2; ch++) {
            int c = 2 * s + ch;
#pragma unroll
            for (int j = 0; j < 3; j++) {
                pw[ch][j] = 0.f;
                int e = t + j * 128;
                if (e < WELEM) {
                    int p = e / 18, r = e - p * 18;
                    int lane = r / 9, k = r - lane * 9;
                    int co = 2 * (g * GP + p) + lane;
                    pw[ch][j] = w2[((size_t)co * 64 + c) * 9 + k];
                }
            }
        }
    };

#pragma unroll 1
    for (int g = 0; g < NG; ++g) {
        ull accA[GP], accB[GP];
#pragma unroll
        for (int p = 0; p < GP; p++) { accA[p] = 0ull; accB[p] = 0ull; }

        prefetch_w(g, 0);
#pragma unroll 1
        for (int s = 0; s < 32; ++s) {
            int b = s & 1;
            // produce conv1 channels 2s, 2s+1 on the (10 x 34) halo region
#pragma unroll
            for (int j = 0; j < 6; j++) {
                int e = t + j * 128;
                if (e < 680) {
                    int ch = e / 340, rr = e - ch * 340;
                    int r = rr / 34, col = rr - r * 34;
                    int c = 2 * s + ch;
                    int gy = y0 + r - 1, gx = x0 + col - 1;
                    float v = 0.f;
                    if (gy >= 0 && gy < H && gx >= 0 && gx < W) {
                        const float* wp = &w1s[c * 10];
                        float a = wp[9];
#pragma unroll
                        for (int dy = 0; dy < 3; dy++)
#pragma unroll
                            for (int dx = 0; dx < 3; dx++)
                                a += xpatch[(r + dy) * XPS + col + dx] * wp[dy * 3 + dx];
                        v = fmaxf(a, 0.f);
                    }
                    cbuf[b][ch][r * PS + col] = v;
                }
            }
            // stage conv2 weights
#pragma unroll
            for (int ch = 0; ch < 2; ch++)
#pragma unroll
                for (int j = 0; j < 3; j++) {
                    int e = t + j * 128;
                    if (e < WELEM) {
                        int p = e / 18, r = e - p * 18;
                        int lane = r / 9, k = r - lane * 9;
                        ws[b][ch][p * 20 + 2 * k + lane] = pw[ch][j];
                    }
                }
            __syncthreads();
            if (s + 1 < 32) prefetch_w(g, s + 1);

            // consume both channels
#pragma unroll
            for (int ch = 0; ch < 2; ch++) {
                const float* pb = cbuf[b][ch];
                ull dup[12];
#pragma unroll
                for (int ky = 0; ky < 3; ky++)
#pragma unroll
                    for (int j = 0; j < 4; j++)
                        dup[ky * 4 + j] = packdup(pb[(ty + ky) * PS + 2 * px + j]);

                const float* wb = ws[b][ch];
#pragma unroll
                for (int p = 0; p < GP; p++) {
                    ull w[9];
                    const ulonglong2* q = reinterpret_cast<const ulonglong2*>(wb + p * 20);
                    ulonglong2 q0 = q[0], q1 = q[1], q2 = q[2], q3 = q[3];
                    w[0] = q0.x; w[1] = q0.y; w[2] = q1.x; w[3] = q1.y;
                    w[4] = q2.x; w[5] = q2.y; w[6] = q3.x; w[7] = q3.y;
                    w[8] = *reinterpret_cast<const ull*>(wb + p * 20 + 16);
#pragma unroll
                    for (int ky = 0; ky < 3; ky++)
#pragma unroll
                        for (int kx = 0; kx < 3; kx++) {
                            ffma2(accA[p], dup[ky * 4 + kx],     w[ky * 3 + kx]);
                            ffma2(accB[p], dup[ky * 4 + kx + 1], w[ky * 3 + kx]);
                        }
                }
            }
        }

        {
            const int oy = y0 + ty;
            const int ox = x0 + 2 * px;
            float* outp = out + (size_t)n * COUT * HW + (size_t)oy * W + ox;
#pragma unroll
            for (int p = 0; p < GP; p++) {
                int co0 = 2 * (g * GP + p);
                float a0, a1, b0v, b1v;
                unpack2(accA[p], a0, a1);
                unpack2(accB[p], b0v, b1v);
                float bi0 = __ldg(&b2[co0]);
                float bi1 = __ldg(&b2[co0 + 1]);
                float r0 = fmaxf(a0 + bi0, 0.f), r1 = fmaxf(b0v + bi0, 0.f);
                float s0 = fmaxf(a1 + bi1, 0.f), s1 = fmaxf(b1v + bi1, 0.f);
                *reinterpret_cast<float2*>(outp + (size_t)co0 * HW) = make_float2(r0, r1);
                *reinterpret_cast<float2*>(outp + (size_t)(co0 + 1) * HW) = make_float2(s0, s1);
            }
        }
        __syncthreads();
    }
}

// ---------------------------------------------------------------------------
// Softmax(81) + 9x9 dynamic conv + nearest upsample into concat channel
// ---------------------------------------------------------------------------
__global__ __launch_bounds__(128)
void softmax_apply_kernel(const float* __restrict__ f, const float* __restrict__ s,
                          float* __restrict__ cat, int H, int W, int ch, int factor)
{
    int idx = blockIdx.x * blockDim.x + threadIdx.x;
    int n = blockIdx.y;
    if (idx >= H * W) return;
    int iy = idx / W, ix = idx - iy * W;

    const float* fn = f + (size_t)n * 81 * H * W + idx;
    float lg[81];
    float mx = -1e30f;
#pragma unroll
    for (int k = 0; k < 81; k++) {
        lg[k] = fn[(size_t)k * H * W];
        mx = fmaxf(mx, lg[k]);
    }
    float sum = 0.f;
#pragma unroll
    for (int k = 0; k < 81; k++) {
        lg[k] = __expf(lg[k] - mx);
        sum += lg[k];
    }
    float inv = 1.f / sum;

    const float* sn = s + (size_t)n * H * W;
    float outv = 0.f;
#pragma unroll
    for (int dy = 0; dy < 9; dy++) {
        int yy = iy + dy - 4;
#pragma unroll
        for (int dx = 0; dx < 9; dx++) {
            int xx = ix + dx - 4;
            float xv = (yy >= 0 && yy < H && xx >= 0 && xx < W)
                         ? sn[(size_t)yy * W + xx] : 0.f;
            outv += lg[dy * 9 + dx] * xv;
        }
    }
    outv *= inv;

    float* cn = cat + ((size_t)n * 5 + ch) * 512 * 512;
    int oy0 = iy * factor, ox0 = ix * factor;
    for (int ry = 0; ry < factor; ry++)
        for (int rx = 0; rx < factor; rx++)
            cn[(size_t)(oy0 + ry) * 512 + ox0 + rx] = outv;
}

// ---------------------------------------------------------------------------
// Launch
// ---------------------------------------------------------------------------
extern "C" void kernel_launch(void* const* d_in, const int* in_sizes, int n_in,
                              void* d_out, int out_size)
{
    const float* x   = (const float*)d_in[0];
    const float* g   = (const float*)d_in[1];
    const float* fWa = (const float*)d_in[2];
    const float* fba = (const float*)d_in[3];
    const float* fWb = (const float*)d_in[4];
    const float* fbb = (const float*)d_in[5];
    const float* fWc = (const float*)d_in[6];
    const float* fbc = (const float*)d_in[7];
    const float* W2a = (const float*)d_in[8];
    const float* b2a = (const float*)d_in[9];
    const float* W2b = (const float*)d_in[10];
    const float* b2b = (const float*)d_in[11];
    float* out = (float*)d_out;

    float *x256, *x128, *x64p, *h1, *h2, *fbuf, *cat;
    cudaGetSymbolAddress((void**)&x256, g_x256);
    cudaGetSymbolAddress((void**)&x128, g_x128);
    cudaGetSymbolAddress((void**)&x64p, g_x64);
    cudaGetSymbolAddress((void**)&h1,   g_h1);
    cudaGetSymbolAddress((void**)&h2,   g_h2);
    cudaGetSymbolAddress((void**)&fbuf, g_f);
    cudaGetSymbolAddress((void**)&cat,  g_cat);

    downsample_kernel<<<dim3((256 * 256 + 255) / 256, 2), 256>>>(x, x256, 256, 256, 2);
    downsample_kernel<<<dim3((128 * 128 + 255) / 256, 2), 256>>>(x, x128, 128, 128, 4);
    downsample_kernel<<<dim3((64 * 64 + 255) / 256, 2), 256>>>(x, x64p, 64, 64, 8);

    const float* sin[5] = { x, x256, x128, x64p, g };
    const int    hs[5]  = { 512, 256, 128, 64, 512 };

    for (int i = 0; i < 5; i++) {
        int H = hs[i], W = H;
        dim3 grid(W / 32, H / 8, 2);
        conv12_kernel<<<grid, 128>>>(
            sin[i], fWa + (size_t)i * 64 * 9, fba + i * 64,
            fWb + (size_t)i * 64 * 64 * 9, fbb + i * 64, h2, H, W);
        conv3x3_kernel<81, false><<<grid, 128>>>(
            h2, fWc + (size_t)i * 81 * 64 * 9, fbc + i * 81, fbuf, 64, H, W);
        int np = H * W;
        softmax_apply_kernel<<<dim3((np + 127) / 128, 2), 128>>>(
            fbuf, sin[i], cat, H, W, i, 512 / H);
    }

    dim3 gridF(512 / 32, 512 / 8, 2);
    conv3x3_kernel<64, true><<<gridF, 128>>>(cat, W2a, b2a, h1, 5, 512, 512);
    conv3x3_kernel<1, false><<<gridF, 128>>>(h1, W2b, b2b, out, 64, 512, 512);
}